// round 1
// baseline (speedup 1.0000x reference)
#include <cuda_runtime.h>
#include <math.h>

#define BB 4
#define TT 2048
#define DD 1024
#define HH 16
#define HD 64
#define MM (BB*TT)           // 8192
#define N3 (3*DD)            // 3072

// Scratch (device globals: allocation-guard-safe)
__device__ float g_q[BB*HH*TT*HD];   // [B,H,T,hd]
__device__ float g_k[BB*HH*TT*HD];
__device__ float g_v[BB*HH*TT*HD];
__device__ float g_y[MM*DD];         // [B,T,D]

// ---------------------------------------------------------------------------
// SGEMM: C[M,N] = A[M,1024] * B[1024,N] + bias
// 128x128x16 tile, 256 threads, 8x8 per thread, register prefetch.
// MODE 0: scatter epilogue into g_q/g_k/g_v head layout. MODE 1: plain C.
// ---------------------------------------------------------------------------
template<int MODE, int N>
__global__ __launch_bounds__(256)
void gemm128(const float* __restrict__ A, const float* __restrict__ Bm,
             const float* __restrict__ bias, float* __restrict__ C)
{
    __shared__ float As[16][128];   // transposed A tile
    __shared__ float Bs[16][128];

    const int tid = threadIdx.x;
    const int tx = tid & 15;
    const int ty = tid >> 4;
    const int bx = blockIdx.x;
    const int by = blockIdx.y;

    const float* Ag = A + (size_t)(by * 128) * 1024;
    const float* Bg = Bm + bx * 128;

    const int arow = tid >> 2;          // 0..63
    const int acol = (tid & 3) << 2;    // 0,4,8,12
    const int brow = tid >> 5;          // 0..7
    const int bcol = (tid & 31) << 2;   // 0..124

    float4 ra0 = *(const float4*)&Ag[arow * 1024 + acol];
    float4 ra1 = *(const float4*)&Ag[(arow + 64) * 1024 + acol];
    float4 rb0 = *(const float4*)&Bg[(size_t)brow * N + bcol];
    float4 rb1 = *(const float4*)&Bg[(size_t)(brow + 8) * N + bcol];

    float acc[8][8];
    #pragma unroll
    for (int i = 0; i < 8; i++)
        #pragma unroll
        for (int j = 0; j < 8; j++) acc[i][j] = 0.0f;

    for (int k0 = 0; k0 < 1024; k0 += 16) {
        As[acol + 0][arow] = ra0.x;
        As[acol + 1][arow] = ra0.y;
        As[acol + 2][arow] = ra0.z;
        As[acol + 3][arow] = ra0.w;
        As[acol + 0][arow + 64] = ra1.x;
        As[acol + 1][arow + 64] = ra1.y;
        As[acol + 2][arow + 64] = ra1.z;
        As[acol + 3][arow + 64] = ra1.w;
        *(float4*)&Bs[brow][bcol]     = rb0;
        *(float4*)&Bs[brow + 8][bcol] = rb1;
        __syncthreads();

        if (k0 + 16 < 1024) {
            const int kn = k0 + 16;
            ra0 = *(const float4*)&Ag[arow * 1024 + kn + acol];
            ra1 = *(const float4*)&Ag[(arow + 64) * 1024 + kn + acol];
            rb0 = *(const float4*)&Bg[(size_t)(kn + brow) * N + bcol];
            rb1 = *(const float4*)&Bg[(size_t)(kn + brow + 8) * N + bcol];
        }

        #pragma unroll
        for (int kk = 0; kk < 16; kk++) {
            float a[8], b[8];
            *(float4*)&a[0] = *(const float4*)&As[kk][ty * 4];
            *(float4*)&a[4] = *(const float4*)&As[kk][64 + ty * 4];
            *(float4*)&b[0] = *(const float4*)&Bs[kk][tx * 4];
            *(float4*)&b[4] = *(const float4*)&Bs[kk][64 + tx * 4];
            #pragma unroll
            for (int i = 0; i < 8; i++)
                #pragma unroll
                for (int j = 0; j < 8; j++)
                    acc[i][j] = fmaf(a[i], b[j], acc[i][j]);
        }
        __syncthreads();
    }

    if (MODE == 0) {
        // scatter into g_q/g_k/g_v as [B,H,T,hd]
        const int sel = bx >> 3;   // 8 n-blocks of 128 per 1024 segment
        float* dst = (sel == 0) ? g_q : ((sel == 1) ? g_k : g_v);
        #pragma unroll
        for (int i2 = 0; i2 < 2; i2++) {
            #pragma unroll
            for (int ii = 0; ii < 4; ii++) {
                const int rl = i2 * 64 + ty * 4 + ii;
                const int m = by * 128 + rl;
                const int b_ = m >> 11;
                const int t_ = m & 2047;
                #pragma unroll
                for (int j2 = 0; j2 < 2; j2++) {
                    const int cl = j2 * 64 + tx * 4;
                    const int n = bx * 128 + cl;
                    const int d = n & 1023;
                    const int hh = d >> 6;
                    const int e = d & 63;
                    float* o = dst + ((size_t)(b_ * 16 + hh) * 2048 + t_) * 64 + e;
                    #pragma unroll
                    for (int jj = 0; jj < 4; jj++)
                        o[jj] = acc[i2 * 4 + ii][j2 * 4 + jj] + bias[n + jj];
                }
            }
        }
    } else {
        #pragma unroll
        for (int i2 = 0; i2 < 2; i2++) {
            #pragma unroll
            for (int ii = 0; ii < 4; ii++) {
                const int m = by * 128 + i2 * 64 + ty * 4 + ii;
                #pragma unroll
                for (int j2 = 0; j2 < 2; j2++) {
                    const int n = bx * 128 + j2 * 64 + tx * 4;
                    float4 r;
                    r.x = acc[i2 * 4 + ii][j2 * 4 + 0] + bias[n + 0];
                    r.y = acc[i2 * 4 + ii][j2 * 4 + 1] + bias[n + 1];
                    r.z = acc[i2 * 4 + ii][j2 * 4 + 2] + bias[n + 2];
                    r.w = acc[i2 * 4 + ii][j2 * 4 + 3] + bias[n + 3];
                    *(float4*)&C[(size_t)m * N + n] = r;
                }
            }
        }
    }
}

// ---------------------------------------------------------------------------
// Flash attention, causal. One CTA = 64 queries of one (b,h).
// 256 threads as 16x16; each thread owns rows {ty+16i} x cols {tx+16j}.
// smem stride 68 -> all inner-loop LDS.128 conflict-free.
// ---------------------------------------------------------------------------
#define SSTR 68

__global__ __launch_bounds__(256)
void attn_kernel()
{
    extern __shared__ float sm[];
    float* Qs = sm;                   // [64][68]
    float* Ks = sm + 64 * SSTR;       // [64][68]
    float* Vt = sm + 2 * 64 * SSTR;   // [64][68]  V transposed: [hd][k]
    float* Ps = sm + 3 * 64 * SSTR;   // [64][68]

    const int tid = threadIdx.x;
    const int tx = tid & 15;
    const int ty = tid >> 4;
    const int qt = blockIdx.x;        // 0..31
    const int h  = blockIdx.y;
    const int b  = blockIdx.z;

    const float* qb = g_q + (size_t)(b * HH + h) * TT * HD;
    const float* kb = g_k + (size_t)(b * HH + h) * TT * HD;
    const float* vb = g_v + (size_t)(b * HH + h) * TT * HD;

    // load Q tile [64 rows][64]
    {
        const int e4 = tid & 15;
        const int r0 = tid >> 4;
        #pragma unroll
        for (int p = 0; p < 4; p++) {
            const int r = r0 + 16 * p;
            float4 v = *(const float4*)&qb[(qt * 64 + r) * 64 + 4 * e4];
            *(float4*)&Qs[r * SSTR + 4 * e4] = v;
        }
    }

    float O[4][4];
    float mi[4], li[4];
    #pragma unroll
    for (int i = 0; i < 4; i++) {
        mi[i] = -INFINITY; li[i] = 0.0f;
        #pragma unroll
        for (int j = 0; j < 4; j++) O[i][j] = 0.0f;
    }
    const float scale = 0.125f;   // 1/sqrt(64)

    for (int kt = 0; kt <= qt; kt++) {
        __syncthreads();   // Q ready (first iter) / prev PV done
        {
            const int e4 = tid & 15;
            const int r0 = tid >> 4;
            #pragma unroll
            for (int p = 0; p < 4; p++) {
                const int r = r0 + 16 * p;
                float4 kv = *(const float4*)&kb[(kt * 64 + r) * 64 + 4 * e4];
                *(float4*)&Ks[r * SSTR + 4 * e4] = kv;
                float4 vv = *(const float4*)&vb[(kt * 64 + r) * 64 + 4 * e4];
                Vt[(4 * e4 + 0) * SSTR + r] = vv.x;
                Vt[(4 * e4 + 1) * SSTR + r] = vv.y;
                Vt[(4 * e4 + 2) * SSTR + r] = vv.z;
                Vt[(4 * e4 + 3) * SSTR + r] = vv.w;
            }
        }
        __syncthreads();

        // S = Q K^T  (dot4 over head dim)
        float S[4][4];
        #pragma unroll
        for (int i = 0; i < 4; i++)
            #pragma unroll
            for (int j = 0; j < 4; j++) S[i][j] = 0.0f;

        #pragma unroll
        for (int e4 = 0; e4 < 16; e4++) {
            float4 qa[4], kf[4];
            #pragma unroll
            for (int i = 0; i < 4; i++)
                qa[i] = *(const float4*)&Qs[(ty + 16 * i) * SSTR + 4 * e4];
            #pragma unroll
            for (int j = 0; j < 4; j++)
                kf[j] = *(const float4*)&Ks[(tx + 16 * j) * SSTR + 4 * e4];
            #pragma unroll
            for (int i = 0; i < 4; i++)
                #pragma unroll
                for (int j = 0; j < 4; j++) {
                    S[i][j] = fmaf(qa[i].x, kf[j].x, S[i][j]);
                    S[i][j] = fmaf(qa[i].y, kf[j].y, S[i][j]);
                    S[i][j] = fmaf(qa[i].z, kf[j].z, S[i][j]);
                    S[i][j] = fmaf(qa[i].w, kf[j].w, S[i][j]);
                }
        }

        if (kt == qt) {
            #pragma unroll
            for (int i = 0; i < 4; i++)
                #pragma unroll
                for (int j = 0; j < 4; j++)
                    S[i][j] = (tx + 16 * j > ty + 16 * i) ? -INFINITY : S[i][j] * scale;
        } else {
            #pragma unroll
            for (int i = 0; i < 4; i++)
                #pragma unroll
                for (int j = 0; j < 4; j++) S[i][j] *= scale;
        }

        // online softmax per row (row spread over 16 tx lanes)
        #pragma unroll
        for (int i = 0; i < 4; i++) {
            float mloc = fmaxf(fmaxf(S[i][0], S[i][1]), fmaxf(S[i][2], S[i][3]));
            #pragma unroll
            for (int msk = 1; msk < 16; msk <<= 1)
                mloc = fmaxf(mloc, __shfl_xor_sync(0xffffffffu, mloc, msk));
            const float mnew = fmaxf(mi[i], mloc);
            const float alpha = __expf(mi[i] - mnew);
            mi[i] = mnew;
            float rs = 0.0f;
            #pragma unroll
            for (int j = 0; j < 4; j++) {
                const float p = __expf(S[i][j] - mnew);
                S[i][j] = p;
                rs += p;
            }
            #pragma unroll
            for (int msk = 1; msk < 16; msk <<= 1)
                rs += __shfl_xor_sync(0xffffffffu, rs, msk);
            li[i] = li[i] * alpha + rs;
            #pragma unroll
            for (int j = 0; j < 4; j++) {
                O[i][j] *= alpha;
                Ps[(ty + 16 * i) * SSTR + tx + 16 * j] = S[i][j];
            }
        }
        __syncthreads();

        // O += P V  (dot4 over key dim)
        #pragma unroll
        for (int k4 = 0; k4 < 16; k4++) {
            float4 pa[4], vf[4];
            #pragma unroll
            for (int i = 0; i < 4; i++)
                pa[i] = *(const float4*)&Ps[(ty + 16 * i) * SSTR + 4 * k4];
            #pragma unroll
            for (int j = 0; j < 4; j++)
                vf[j] = *(const float4*)&Vt[(tx + 16 * j) * SSTR + 4 * k4];
            #pragma unroll
            for (int i = 0; i < 4; i++)
                #pragma unroll
                for (int j = 0; j < 4; j++) {
                    O[i][j] = fmaf(pa[i].x, vf[j].x, O[i][j]);
                    O[i][j] = fmaf(pa[i].y, vf[j].y, O[i][j]);
                    O[i][j] = fmaf(pa[i].z, vf[j].z, O[i][j]);
                    O[i][j] = fmaf(pa[i].w, vf[j].w, O[i][j]);
                }
        }
    }

    // normalize + store y[b,t,d]
    #pragma unroll
    for (int i = 0; i < 4; i++) {
        const float inv = 1.0f / li[i];
        const int t = qt * 64 + ty + 16 * i;
        float* yrow = g_y + ((size_t)(b * TT + t)) * DD + h * HD;
        #pragma unroll
        for (int j = 0; j < 4; j++)
            yrow[tx + 16 * j] = O[i][j] * inv;
    }
}

// ---------------------------------------------------------------------------
extern "C" void kernel_launch(void* const* d_in, const int* in_sizes, int n_in,
                              void* d_out, int out_size)
{
    (void)in_sizes; (void)n_in; (void)out_size;
    const float* x      = (const float*)d_in[0];
    const float* W_attn = (const float*)d_in[1];
    const float* b_attn = (const float*)d_in[2];
    const float* W_proj = (const float*)d_in[3];
    const float* b_proj = (const float*)d_in[4];
    float* out = (float*)d_out;

    // 1) QKV projection + head-layout scatter
    dim3 g1(N3 / 128, MM / 128);   // (24, 64)
    gemm128<0, N3><<<g1, 256>>>(x, W_attn, b_attn, nullptr);

    // 2) causal flash attention
    const int smem = 4 * 64 * SSTR * (int)sizeof(float);   // 69632 B
    cudaFuncSetAttribute(attn_kernel, cudaFuncAttributeMaxDynamicSharedMemorySize, smem);
    attn_kernel<<<dim3(TT / 64, HH, BB), 256, smem>>>();

    // 3) output projection
    float* gy = nullptr;
    cudaGetSymbolAddress((void**)&gy, g_y);
    dim3 g2(DD / 128, MM / 128);   // (8, 64)
    gemm128<1, DD><<<g2, 256>>>(gy, W_proj, b_proj, out);
}

// round 3
// speedup vs baseline: 1.5051x; 1.5051x over previous
#include <cuda_runtime.h>
#include <math.h>
#include <stdint.h>

#define BB 4
#define TT 2048
#define DD 1024
#define HH 16
#define HD 64
#define MM (BB*TT)           // 8192
#define N3 (3*DD)            // 3072

// Scratch (device globals: allocation-guard-safe)
__device__ float g_q[BB*HH*TT*HD];   // [B,H,T,hd]
__device__ float g_k[BB*HH*TT*HD];
__device__ float g_v[BB*HH*TT*HD];
__device__ float g_y[MM*DD];         // [B,T,D]

__device__ __forceinline__ float tf32r(float x) {
    uint32_t u;
    asm("cvt.rna.tf32.f32 %0, %1;" : "=r"(u) : "f"(x));
    return __uint_as_float(u);
}
__device__ __forceinline__ uint32_t f2b(float x) { return __float_as_uint(x); }

#define MMA_TF32(d, a, b) \
    asm volatile("mma.sync.aligned.m16n8k8.row.col.f32.tf32.tf32.f32 " \
        "{%0,%1,%2,%3}, {%4,%5,%6,%7}, {%8,%9}, {%0,%1,%2,%3};" \
        : "+f"((d)[0]), "+f"((d)[1]), "+f"((d)[2]), "+f"((d)[3]) \
        : "r"((a)[0]), "r"((a)[1]), "r"((a)[2]), "r"((a)[3]), \
          "r"((b)[0]), "r"((b)[1]))

// ---------------------------------------------------------------------------
// Tensor-core TF32 GEMM: C[M,N] = A[M,1024] * B[1024,N] + bias
// CTA 128x128, 8 warps (2M x 4N), warp tile 64x32, mma m16n8k8.
// Smem: As transposed [k][m] stride 136 (conflict-free frag loads),
//       Bs [k][n] stride 136. K staged by 16, double buffered.
// MODE 0: scatter epilogue into g_q/g_k/g_v head layout. MODE 1: plain C.
// ---------------------------------------------------------------------------
#define KSTAGE 16
#define SSTRIDE 136
#define BUFSZ (KSTAGE * SSTRIDE)          // floats per matrix per buffer
#define SMEM_GEMM (4 * BUFSZ * 4)         // bytes: 2 bufs x (A+B)

template<int MODE, int NTOT>
__global__ __launch_bounds__(256)
void mma_gemm(const float* __restrict__ A, const float* __restrict__ B,
              const float* __restrict__ bias, float* __restrict__ C)
{
    extern __shared__ float sm[];
    float* As = sm;                 // [2][16][136]
    float* Bs = sm + 2 * BUFSZ;     // [2][16][136]

    const int tid = threadIdx.x;
    const int lane = tid & 31;
    const int wid = tid >> 5;
    const int warp_m = wid >> 2;    // 0..1
    const int warp_n = wid & 3;     // 0..3
    const int g = lane >> 2;        // 0..7
    const int tg = lane & 3;        // 0..3
    const int bx = blockIdx.x, by = blockIdx.y;

    const float* Ag = A + (size_t)(by * 128) * 1024;
    const float* Bg = B + bx * 128;

    // global->smem mapping
    const int am0 = tid >> 2;             // 0..63
    const int am1 = am0 + 64;
    const int akc = (tid & 3) << 2;       // 0,4,8,12
    const int bk0 = tid >> 5;             // 0..7
    const int bk1 = bk0 + 8;
    const int bnc = (tid & 31) << 2;      // 0..124

    float acc[4][4][4];
    #pragma unroll
    for (int i = 0; i < 4; i++)
        #pragma unroll
        for (int j = 0; j < 4; j++)
            #pragma unroll
            for (int r = 0; r < 4; r++) acc[i][j][r] = 0.0f;

    float4 ra0 = *(const float4*)&Ag[(size_t)am0 * 1024 + akc];
    float4 ra1 = *(const float4*)&Ag[(size_t)am1 * 1024 + akc];
    float4 rb0 = *(const float4*)&Bg[(size_t)bk0 * NTOT + bnc];
    float4 rb1 = *(const float4*)&Bg[(size_t)bk1 * NTOT + bnc];

    for (int s = 0; s < 1024 / KSTAGE; s++) {
        const int buf = s & 1;
        float* Ab = As + buf * BUFSZ;
        float* Bb = Bs + buf * BUFSZ;

        // store stage (tf32-rounded)
        Ab[(akc + 0) * SSTRIDE + am0] = tf32r(ra0.x);
        Ab[(akc + 1) * SSTRIDE + am0] = tf32r(ra0.y);
        Ab[(akc + 2) * SSTRIDE + am0] = tf32r(ra0.z);
        Ab[(akc + 3) * SSTRIDE + am0] = tf32r(ra0.w);
        Ab[(akc + 0) * SSTRIDE + am1] = tf32r(ra1.x);
        Ab[(akc + 1) * SSTRIDE + am1] = tf32r(ra1.y);
        Ab[(akc + 2) * SSTRIDE + am1] = tf32r(ra1.z);
        Ab[(akc + 3) * SSTRIDE + am1] = tf32r(ra1.w);
        float4 q0, q1;
        q0.x = tf32r(rb0.x); q0.y = tf32r(rb0.y); q0.z = tf32r(rb0.z); q0.w = tf32r(rb0.w);
        q1.x = tf32r(rb1.x); q1.y = tf32r(rb1.y); q1.z = tf32r(rb1.z); q1.w = tf32r(rb1.w);
        *(float4*)&Bb[bk0 * SSTRIDE + bnc] = q0;
        *(float4*)&Bb[bk1 * SSTRIDE + bnc] = q1;
        __syncthreads();

        if (s < 1024 / KSTAGE - 1) {
            const int kb = (s + 1) * KSTAGE;
            ra0 = *(const float4*)&Ag[(size_t)am0 * 1024 + kb + akc];
            ra1 = *(const float4*)&Ag[(size_t)am1 * 1024 + kb + akc];
            rb0 = *(const float4*)&Bg[(size_t)(kb + bk0) * NTOT + bnc];
            rb1 = *(const float4*)&Bg[(size_t)(kb + bk1) * NTOT + bnc];
        }

        // compute: 2 k8 sub-steps
        #pragma unroll
        for (int ks = 0; ks < 2; ks++) {
            const int k8 = ks * 8;
            uint32_t af[4][4];
            #pragma unroll
            for (int mi = 0; mi < 4; mi++) {
                const int bm = warp_m * 64 + mi * 16;
                af[mi][0] = f2b(Ab[(k8 + tg) * SSTRIDE + bm + g]);
                af[mi][1] = f2b(Ab[(k8 + tg) * SSTRIDE + bm + g + 8]);
                af[mi][2] = f2b(Ab[(k8 + tg + 4) * SSTRIDE + bm + g]);
                af[mi][3] = f2b(Ab[(k8 + tg + 4) * SSTRIDE + bm + g + 8]);
            }
            uint32_t bf[4][2];
            #pragma unroll
            for (int ni = 0; ni < 4; ni++) {
                const int bn = warp_n * 32 + ni * 8;
                bf[ni][0] = f2b(Bb[(k8 + tg) * SSTRIDE + bn + g]);
                bf[ni][1] = f2b(Bb[(k8 + tg + 4) * SSTRIDE + bn + g]);
            }
            #pragma unroll
            for (int mi = 0; mi < 4; mi++)
                #pragma unroll
                for (int ni = 0; ni < 4; ni++)
                    MMA_TF32(acc[mi][ni], af[mi], bf[ni]);
        }
    }

    // epilogue
    #pragma unroll
    for (int mi = 0; mi < 4; mi++) {
        #pragma unroll
        for (int ni = 0; ni < 4; ni++) {
            const int n = bx * 128 + warp_n * 32 + ni * 8 + 2 * tg;
            const float b0 = bias[n], b1 = bias[n + 1];
            #pragma unroll
            for (int p = 0; p < 2; p++) {
                const int row = warp_m * 64 + mi * 16 + g + p * 8;
                const int m = by * 128 + row;
                float2 v;
                v.x = acc[mi][ni][2 * p + 0] + b0;
                v.y = acc[mi][ni][2 * p + 1] + b1;
                if (MODE == 0) {
                    const int b_ = m >> 11;
                    const int t_ = m & 2047;
                    const int sel = n >> 10;
                    const int d = n & 1023;
                    float* dst = (sel == 0) ? g_q : ((sel == 1) ? g_k : g_v);
                    *(float2*)&dst[((size_t)(b_ * 16 + (d >> 6)) * 2048 + t_) * 64 + (d & 63)] = v;
                } else {
                    *(float2*)&C[(size_t)m * NTOT + n] = v;
                }
            }
        }
    }
}

// ---------------------------------------------------------------------------
// Flash attention, causal (unchanged). One CTA = 64 queries of one (b,h).
// ---------------------------------------------------------------------------
#define SSTR 68

__global__ __launch_bounds__(256)
void attn_kernel()
{
    extern __shared__ float smf[];
    float* Qs = smf;
    float* Ks = smf + 64 * SSTR;
    float* Vt = smf + 2 * 64 * SSTR;
    float* Ps = smf + 3 * 64 * SSTR;

    const int tid = threadIdx.x;
    const int tx = tid & 15;
    const int ty = tid >> 4;
    const int qt = blockIdx.x;
    const int h  = blockIdx.y;
    const int b  = blockIdx.z;

    const float* qb = g_q + (size_t)(b * HH + h) * TT * HD;
    const float* kb = g_k + (size_t)(b * HH + h) * TT * HD;
    const float* vb = g_v + (size_t)(b * HH + h) * TT * HD;

    {
        const int e4 = tid & 15;
        const int r0 = tid >> 4;
        #pragma unroll
        for (int p = 0; p < 4; p++) {
            const int r = r0 + 16 * p;
            float4 v = *(const float4*)&qb[(qt * 64 + r) * 64 + 4 * e4];
            *(float4*)&Qs[r * SSTR + 4 * e4] = v;
        }
    }

    float O[4][4];
    float mi[4], li[4];
    #pragma unroll
    for (int i = 0; i < 4; i++) {
        mi[i] = -INFINITY; li[i] = 0.0f;
        #pragma unroll
        for (int j = 0; j < 4; j++) O[i][j] = 0.0f;
    }
    const float scale = 0.125f;

    for (int kt = 0; kt <= qt; kt++) {
        __syncthreads();
        {
            const int e4 = tid & 15;
            const int r0 = tid >> 4;
            #pragma unroll
            for (int p = 0; p < 4; p++) {
                const int r = r0 + 16 * p;
                float4 kv = *(const float4*)&kb[(kt * 64 + r) * 64 + 4 * e4];
                *(float4*)&Ks[r * SSTR + 4 * e4] = kv;
                float4 vv = *(const float4*)&vb[(kt * 64 + r) * 64 + 4 * e4];
                Vt[(4 * e4 + 0) * SSTR + r] = vv.x;
                Vt[(4 * e4 + 1) * SSTR + r] = vv.y;
                Vt[(4 * e4 + 2) * SSTR + r] = vv.z;
                Vt[(4 * e4 + 3) * SSTR + r] = vv.w;
            }
        }
        __syncthreads();

        float S[4][4];
        #pragma unroll
        for (int i = 0; i < 4; i++)
            #pragma unroll
            for (int j = 0; j < 4; j++) S[i][j] = 0.0f;

        #pragma unroll
        for (int e4 = 0; e4 < 16; e4++) {
            float4 qa[4], kf[4];
            #pragma unroll
            for (int i = 0; i < 4; i++)
                qa[i] = *(const float4*)&Qs[(ty + 16 * i) * SSTR + 4 * e4];
            #pragma unroll
            for (int j = 0; j < 4; j++)
                kf[j] = *(const float4*)&Ks[(tx + 16 * j) * SSTR + 4 * e4];
            #pragma unroll
            for (int i = 0; i < 4; i++)
                #pragma unroll
                for (int j = 0; j < 4; j++) {
                    S[i][j] = fmaf(qa[i].x, kf[j].x, S[i][j]);
                    S[i][j] = fmaf(qa[i].y, kf[j].y, S[i][j]);
                    S[i][j] = fmaf(qa[i].z, kf[j].z, S[i][j]);
                    S[i][j] = fmaf(qa[i].w, kf[j].w, S[i][j]);
                }
        }

        if (kt == qt) {
            #pragma unroll
            for (int i = 0; i < 4; i++)
                #pragma unroll
                for (int j = 0; j < 4; j++)
                    S[i][j] = (tx + 16 * j > ty + 16 * i) ? -INFINITY : S[i][j] * scale;
        } else {
            #pragma unroll
            for (int i = 0; i < 4; i++)
                #pragma unroll
                for (int j = 0; j < 4; j++) S[i][j] *= scale;
        }

        #pragma unroll
        for (int i = 0; i < 4; i++) {
            float mloc = fmaxf(fmaxf(S[i][0], S[i][1]), fmaxf(S[i][2], S[i][3]));
            #pragma unroll
            for (int msk = 1; msk < 16; msk <<= 1)
                mloc = fmaxf(mloc, __shfl_xor_sync(0xffffffffu, mloc, msk));
            const float mnew = fmaxf(mi[i], mloc);
            const float alpha = __expf(mi[i] - mnew);
            mi[i] = mnew;
            float rs = 0.0f;
            #pragma unroll
            for (int j = 0; j < 4; j++) {
                const float p = __expf(S[i][j] - mnew);
                S[i][j] = p;
                rs += p;
            }
            #pragma unroll
            for (int msk = 1; msk < 16; msk <<= 1)
                rs += __shfl_xor_sync(0xffffffffu, rs, msk);
            li[i] = li[i] * alpha + rs;
            #pragma unroll
            for (int j = 0; j < 4; j++) {
                O[i][j] *= alpha;
                Ps[(ty + 16 * i) * SSTR + tx + 16 * j] = S[i][j];
            }
        }
        __syncthreads();

        #pragma unroll
        for (int k4 = 0; k4 < 16; k4++) {
            float4 pa[4], vf[4];
            #pragma unroll
            for (int i = 0; i < 4; i++)
                pa[i] = *(const float4*)&Ps[(ty + 16 * i) * SSTR + 4 * k4];
            #pragma unroll
            for (int j = 0; j < 4; j++)
                vf[j] = *(const float4*)&Vt[(tx + 16 * j) * SSTR + 4 * k4];
            #pragma unroll
            for (int i = 0; i < 4; i++)
                #pragma unroll
                for (int j = 0; j < 4; j++) {
                    O[i][j] = fmaf(pa[i].x, vf[j].x, O[i][j]);
                    O[i][j] = fmaf(pa[i].y, vf[j].y, O[i][j]);
                    O[i][j] = fmaf(pa[i].z, vf[j].z, O[i][j]);
                    O[i][j] = fmaf(pa[i].w, vf[j].w, O[i][j]);
                }
        }
    }

    #pragma unroll
    for (int i = 0; i < 4; i++) {
        const float inv = 1.0f / li[i];
        const int t = qt * 64 + ty + 16 * i;
        float* yrow = g_y + ((size_t)(b * TT + t)) * DD + h * HD;
        #pragma unroll
        for (int j = 0; j < 4; j++)
            yrow[tx + 16 * j] = O[i][j] * inv;
    }
}

// ---------------------------------------------------------------------------
extern "C" void kernel_launch(void* const* d_in, const int* in_sizes, int n_in,
                              void* d_out, int out_size)
{
    (void)in_sizes; (void)n_in; (void)out_size;
    const float* x      = (const float*)d_in[0];
    const float* W_attn = (const float*)d_in[1];
    const float* b_attn = (const float*)d_in[2];
    const float* W_proj = (const float*)d_in[3];
    const float* b_proj = (const float*)d_in[4];
    float* out = (float*)d_out;

    float* gy = nullptr;
    cudaGetSymbolAddress((void**)&gy, g_y);

    static bool attr_done = false;
    if (!attr_done) {
        cudaFuncSetAttribute(mma_gemm<0, N3>, cudaFuncAttributeMaxDynamicSharedMemorySize, SMEM_GEMM);
        cudaFuncSetAttribute(mma_gemm<1, DD>, cudaFuncAttributeMaxDynamicSharedMemorySize, SMEM_GEMM);
        cudaFuncSetAttribute(attn_kernel, cudaFuncAttributeMaxDynamicSharedMemorySize,
                             4 * 64 * SSTR * (int)sizeof(float));
        attr_done = true;
    }

    // 1) QKV projection (mma.sync tf32) + head-layout scatter
    mma_gemm<0, N3><<<dim3(N3 / 128, MM / 128), 256, SMEM_GEMM>>>(x, W_attn, b_attn, nullptr);

    // 2) causal flash attention (fp32 FFMA)
    const int smem_attn = 4 * 64 * SSTR * (int)sizeof(float);
    attn_kernel<<<dim3(TT / 64, HH, BB), 256, smem_attn>>>();

    // 3) output projection (mma.sync tf32)
    mma_gemm<1, DD><<<dim3(DD / 128, MM / 128), 256, SMEM_GEMM>>>(gy, W_proj, b_proj, out);
}

// round 4
// speedup vs baseline: 2.4371x; 1.6192x over previous
#include <cuda_runtime.h>
#include <math.h>
#include <stdint.h>

#define BB 4
#define TT 2048
#define DD 1024
#define HH 16
#define HD 64
#define MM (BB*TT)           // 8192
#define N3 (3*DD)            // 3072

// Scratch (device globals: allocation-guard-safe)
__device__ float g_q[BB*HH*TT*HD];   // [B,H,T,hd]
__device__ float g_k[BB*HH*TT*HD];
__device__ float g_v[BB*HH*TT*HD];
__device__ float g_y[MM*DD];         // [B,T,D]

__device__ __forceinline__ float tf32r(float x) {
    uint32_t u;
    asm("cvt.rna.tf32.f32 %0, %1;" : "=r"(u) : "f"(x));
    return __uint_as_float(u);
}
__device__ __forceinline__ uint32_t f2b(float x) { return __float_as_uint(x); }

#define MMA_TF32(d, a, b) \
    asm volatile("mma.sync.aligned.m16n8k8.row.col.f32.tf32.tf32.f32 " \
        "{%0,%1,%2,%3}, {%4,%5,%6,%7}, {%8,%9}, {%0,%1,%2,%3};" \
        : "+f"((d)[0]), "+f"((d)[1]), "+f"((d)[2]), "+f"((d)[3]) \
        : "r"((a)[0]), "r"((a)[1]), "r"((a)[2]), "r"((a)[3]), \
          "r"((b)[0]), "r"((b)[1]))

// ---------------------------------------------------------------------------
// Tensor-core TF32 GEMM (unchanged from R3): C[M,N] = A[M,1024]*B[1024,N]+bias
// ---------------------------------------------------------------------------
#define KSTAGE 16
#define SSTRIDE 136
#define BUFSZ (KSTAGE * SSTRIDE)
#define SMEM_GEMM (4 * BUFSZ * 4)

template<int MODE, int NTOT>
__global__ __launch_bounds__(256)
void mma_gemm(const float* __restrict__ A, const float* __restrict__ B,
              const float* __restrict__ bias, float* __restrict__ C)
{
    extern __shared__ float sm[];
    float* As = sm;
    float* Bs = sm + 2 * BUFSZ;

    const int tid = threadIdx.x;
    const int lane = tid & 31;
    const int wid = tid >> 5;
    const int warp_m = wid >> 2;
    const int warp_n = wid & 3;
    const int g = lane >> 2;
    const int tg = lane & 3;
    const int bx = blockIdx.x, by = blockIdx.y;

    const float* Ag = A + (size_t)(by * 128) * 1024;
    const float* Bg = B + bx * 128;

    const int am0 = tid >> 2;
    const int am1 = am0 + 64;
    const int akc = (tid & 3) << 2;
    const int bk0 = tid >> 5;
    const int bk1 = bk0 + 8;
    const int bnc = (tid & 31) << 2;

    float acc[4][4][4];
    #pragma unroll
    for (int i = 0; i < 4; i++)
        #pragma unroll
        for (int j = 0; j < 4; j++)
            #pragma unroll
            for (int r = 0; r < 4; r++) acc[i][j][r] = 0.0f;

    float4 ra0 = *(const float4*)&Ag[(size_t)am0 * 1024 + akc];
    float4 ra1 = *(const float4*)&Ag[(size_t)am1 * 1024 + akc];
    float4 rb0 = *(const float4*)&Bg[(size_t)bk0 * NTOT + bnc];
    float4 rb1 = *(const float4*)&Bg[(size_t)bk1 * NTOT + bnc];

    for (int s = 0; s < 1024 / KSTAGE; s++) {
        const int buf = s & 1;
        float* Ab = As + buf * BUFSZ;
        float* Bb = Bs + buf * BUFSZ;

        Ab[(akc + 0) * SSTRIDE + am0] = tf32r(ra0.x);
        Ab[(akc + 1) * SSTRIDE + am0] = tf32r(ra0.y);
        Ab[(akc + 2) * SSTRIDE + am0] = tf32r(ra0.z);
        Ab[(akc + 3) * SSTRIDE + am0] = tf32r(ra0.w);
        Ab[(akc + 0) * SSTRIDE + am1] = tf32r(ra1.x);
        Ab[(akc + 1) * SSTRIDE + am1] = tf32r(ra1.y);
        Ab[(akc + 2) * SSTRIDE + am1] = tf32r(ra1.z);
        Ab[(akc + 3) * SSTRIDE + am1] = tf32r(ra1.w);
        float4 q0, q1;
        q0.x = tf32r(rb0.x); q0.y = tf32r(rb0.y); q0.z = tf32r(rb0.z); q0.w = tf32r(rb0.w);
        q1.x = tf32r(rb1.x); q1.y = tf32r(rb1.y); q1.z = tf32r(rb1.z); q1.w = tf32r(rb1.w);
        *(float4*)&Bb[bk0 * SSTRIDE + bnc] = q0;
        *(float4*)&Bb[bk1 * SSTRIDE + bnc] = q1;
        __syncthreads();

        if (s < 1024 / KSTAGE - 1) {
            const int kb = (s + 1) * KSTAGE;
            ra0 = *(const float4*)&Ag[(size_t)am0 * 1024 + kb + akc];
            ra1 = *(const float4*)&Ag[(size_t)am1 * 1024 + kb + akc];
            rb0 = *(const float4*)&Bg[(size_t)(kb + bk0) * NTOT + bnc];
            rb1 = *(const float4*)&Bg[(size_t)(kb + bk1) * NTOT + bnc];
        }

        #pragma unroll
        for (int ks = 0; ks < 2; ks++) {
            const int k8 = ks * 8;
            uint32_t af[4][4];
            #pragma unroll
            for (int mi = 0; mi < 4; mi++) {
                const int bm = warp_m * 64 + mi * 16;
                af[mi][0] = f2b(Ab[(k8 + tg) * SSTRIDE + bm + g]);
                af[mi][1] = f2b(Ab[(k8 + tg) * SSTRIDE + bm + g + 8]);
                af[mi][2] = f2b(Ab[(k8 + tg + 4) * SSTRIDE + bm + g]);
                af[mi][3] = f2b(Ab[(k8 + tg + 4) * SSTRIDE + bm + g + 8]);
            }
            uint32_t bf[4][2];
            #pragma unroll
            for (int ni = 0; ni < 4; ni++) {
                const int bn = warp_n * 32 + ni * 8;
                bf[ni][0] = f2b(Bb[(k8 + tg) * SSTRIDE + bn + g]);
                bf[ni][1] = f2b(Bb[(k8 + tg + 4) * SSTRIDE + bn + g]);
            }
            #pragma unroll
            for (int mi = 0; mi < 4; mi++)
                #pragma unroll
                for (int ni = 0; ni < 4; ni++)
                    MMA_TF32(acc[mi][ni], af[mi], bf[ni]);
        }
    }

    #pragma unroll
    for (int mi = 0; mi < 4; mi++) {
        #pragma unroll
        for (int ni = 0; ni < 4; ni++) {
            const int n = bx * 128 + warp_n * 32 + ni * 8 + 2 * tg;
            const float b0 = bias[n], b1 = bias[n + 1];
            #pragma unroll
            for (int p = 0; p < 2; p++) {
                const int row = warp_m * 64 + mi * 16 + g + p * 8;
                const int m = by * 128 + row;
                float2 v;
                v.x = acc[mi][ni][2 * p + 0] + b0;
                v.y = acc[mi][ni][2 * p + 1] + b1;
                if (MODE == 0) {
                    const int b_ = m >> 11;
                    const int t_ = m & 2047;
                    const int sel = n >> 10;
                    const int d = n & 1023;
                    float* dst = (sel == 0) ? g_q : ((sel == 1) ? g_k : g_v);
                    *(float2*)&dst[((size_t)(b_ * 16 + (d >> 6)) * 2048 + t_) * 64 + (d & 63)] = v;
                } else {
                    *(float2*)&C[(size_t)m * NTOT + n] = v;
                }
            }
        }
    }
}

// ---------------------------------------------------------------------------
// Tensor-core flash attention (causal, tf32 mma). CTA = 128 queries of (b,h),
// 8 warps, warp owns 16 query rows. Key tiles of 64. All smem frag-load
// patterns bank-conflict-free with stride 68.
// ---------------------------------------------------------------------------
#define ASTR 68
#define SMEM_ATTN ((2 * 64 * ASTR + 8 * 16 * ASTR) * 4)   // 69632 B

__global__ __launch_bounds__(256)
void attn_tc()
{
    extern __shared__ float smf[];
    float* Ks = smf;                        // [64][68]  K[key][hd]
    float* Vs = smf + 64 * ASTR;            // [64][68]  V[key][hd]
    float* Ps = smf + 2 * 64 * ASTR;        // [8][16][68]  per-warp P / Q-stage

    const int tid  = threadIdx.x;
    const int lane = tid & 31;
    const int wid  = tid >> 5;
    const int g    = lane >> 2;
    const int tg   = lane & 3;
    const int qt = blockIdx.x;              // 0..15 (128 queries)
    const int h  = blockIdx.y;
    const int b  = blockIdx.z;

    const float* qb = g_q + (size_t)(b * HH + h) * TT * HD;
    const float* kb = g_k + (size_t)(b * HH + h) * TT * HD;
    const float* vb = g_v + (size_t)(b * HH + h) * TT * HD;

    float* Pw = Ps + wid * 16 * ASTR;

    // ---- load Q fragments into registers (once) ----
    uint32_t Qf[8][4];
    {
        const int r = lane >> 1;            // 0..15
        const int c = (lane & 1) * 32;
        const float* qrow = qb + (size_t)(qt * 128 + wid * 16 + r) * 64 + c;
        #pragma unroll
        for (int i = 0; i < 8; i++) {
            float4 v = *(const float4*)&qrow[i * 4];
            v.x = tf32r(v.x); v.y = tf32r(v.y); v.z = tf32r(v.z); v.w = tf32r(v.w);
            *(float4*)&Pw[r * ASTR + c + i * 4] = v;
        }
        __syncwarp();
        #pragma unroll
        for (int ks = 0; ks < 8; ks++) {
            Qf[ks][0] = f2b(Pw[g * ASTR + ks * 8 + tg]);
            Qf[ks][1] = f2b(Pw[(g + 8) * ASTR + ks * 8 + tg]);
            Qf[ks][2] = f2b(Pw[g * ASTR + ks * 8 + tg + 4]);
            Qf[ks][3] = f2b(Pw[(g + 8) * ASTR + ks * 8 + tg + 4]);
        }
    }

    float O[8][4];
    #pragma unroll
    for (int ni = 0; ni < 8; ni++)
        #pragma unroll
        for (int r = 0; r < 4; r++) O[ni][r] = 0.0f;
    float mi0 = -INFINITY, mi1 = -INFINITY, li0 = 0.0f, li1 = 0.0f;

    const int row0 = qt * 128 + wid * 16 + g;
    const int row1 = row0 + 8;
    const int wrow_min = qt * 128 + wid * 16;
    const float scale = 0.125f;   // 1/sqrt(64)
    const int nkt = 2 * qt + 2;

    for (int kt = 0; kt < nkt; kt++) {
        __syncthreads();   // prev tile frag reads done before overwrite
        {
            const int r = tid >> 2;              // 0..63
            const int c = (tid & 3) << 4;        // 0,16,32,48
            const float* krow = kb + (size_t)(kt * 64 + r) * 64 + c;
            const float* vrow = vb + (size_t)(kt * 64 + r) * 64 + c;
            #pragma unroll
            for (int i = 0; i < 4; i++) {
                float4 kv = *(const float4*)&krow[i * 4];
                kv.x = tf32r(kv.x); kv.y = tf32r(kv.y); kv.z = tf32r(kv.z); kv.w = tf32r(kv.w);
                *(float4*)&Ks[r * ASTR + c + i * 4] = kv;
                float4 vv = *(const float4*)&vrow[i * 4];
                vv.x = tf32r(vv.x); vv.y = tf32r(vv.y); vv.z = tf32r(vv.z); vv.w = tf32r(vv.w);
                *(float4*)&Vs[r * ASTR + c + i * 4] = vv;
            }
        }
        __syncthreads();

        // ---- S = Q K^T ----
        float S[8][4];
        #pragma unroll
        for (int ni = 0; ni < 8; ni++)
            #pragma unroll
            for (int r = 0; r < 4; r++) S[ni][r] = 0.0f;

        #pragma unroll
        for (int ks = 0; ks < 8; ks++) {
            uint32_t bf[8][2];
            #pragma unroll
            for (int ni = 0; ni < 8; ni++) {
                bf[ni][0] = f2b(Ks[(ni * 8 + g) * ASTR + ks * 8 + tg]);
                bf[ni][1] = f2b(Ks[(ni * 8 + g) * ASTR + ks * 8 + tg + 4]);
            }
            #pragma unroll
            for (int ni = 0; ni < 8; ni++)
                MMA_TF32(S[ni], Qf[ks], bf[ni]);
        }

        // ---- scale + causal mask ----
        if (kt * 64 + 63 > wrow_min) {
            #pragma unroll
            for (int ni = 0; ni < 8; ni++) {
                const int c0 = kt * 64 + ni * 8 + 2 * tg;
                S[ni][0] = (c0     > row0) ? -INFINITY : S[ni][0] * scale;
                S[ni][1] = (c0 + 1 > row0) ? -INFINITY : S[ni][1] * scale;
                S[ni][2] = (c0     > row1) ? -INFINITY : S[ni][2] * scale;
                S[ni][3] = (c0 + 1 > row1) ? -INFINITY : S[ni][3] * scale;
            }
        } else {
            #pragma unroll
            for (int ni = 0; ni < 8; ni++) {
                S[ni][0] *= scale; S[ni][1] *= scale;
                S[ni][2] *= scale; S[ni][3] *= scale;
            }
        }

        // ---- online softmax (rows g and g+8; quad-shuffle reduce) ----
        float m0 = -INFINITY, m1 = -INFINITY;
        #pragma unroll
        for (int ni = 0; ni < 8; ni++) {
            m0 = fmaxf(m0, fmaxf(S[ni][0], S[ni][1]));
            m1 = fmaxf(m1, fmaxf(S[ni][2], S[ni][3]));
        }
        m0 = fmaxf(m0, __shfl_xor_sync(0xffffffffu, m0, 1));
        m0 = fmaxf(m0, __shfl_xor_sync(0xffffffffu, m0, 2));
        m1 = fmaxf(m1, __shfl_xor_sync(0xffffffffu, m1, 1));
        m1 = fmaxf(m1, __shfl_xor_sync(0xffffffffu, m1, 2));
        const float mn0 = fmaxf(mi0, m0);
        const float mn1 = fmaxf(mi1, m1);
        const float a0 = __expf(mi0 - mn0);
        const float a1 = __expf(mi1 - mn1);
        mi0 = mn0; mi1 = mn1;

        float rs0 = 0.0f, rs1 = 0.0f;
        #pragma unroll
        for (int ni = 0; ni < 8; ni++) {
            const float p00 = __expf(S[ni][0] - mn0);
            const float p01 = __expf(S[ni][1] - mn0);
            const float p10 = __expf(S[ni][2] - mn1);
            const float p11 = __expf(S[ni][3] - mn1);
            rs0 += p00 + p01;
            rs1 += p10 + p11;
            float2 t0; t0.x = tf32r(p00); t0.y = tf32r(p01);
            *(float2*)&Pw[g * ASTR + ni * 8 + 2 * tg] = t0;
            float2 t1; t1.x = tf32r(p10); t1.y = tf32r(p11);
            *(float2*)&Pw[(g + 8) * ASTR + ni * 8 + 2 * tg] = t1;
            O[ni][0] *= a0; O[ni][1] *= a0;
            O[ni][2] *= a1; O[ni][3] *= a1;
        }
        rs0 += __shfl_xor_sync(0xffffffffu, rs0, 1);
        rs0 += __shfl_xor_sync(0xffffffffu, rs0, 2);
        rs1 += __shfl_xor_sync(0xffffffffu, rs1, 1);
        rs1 += __shfl_xor_sync(0xffffffffu, rs1, 2);
        li0 = li0 * a0 + rs0;
        li1 = li1 * a1 + rs1;
        __syncwarp();

        // ---- O += P V ----
        #pragma unroll
        for (int ks = 0; ks < 8; ks++) {
            uint32_t af[4];
            af[0] = f2b(Pw[g * ASTR + ks * 8 + tg]);
            af[1] = f2b(Pw[(g + 8) * ASTR + ks * 8 + tg]);
            af[2] = f2b(Pw[g * ASTR + ks * 8 + tg + 4]);
            af[3] = f2b(Pw[(g + 8) * ASTR + ks * 8 + tg + 4]);
            uint32_t bf[8][2];
            #pragma unroll
            for (int ni = 0; ni < 8; ni++) {
                bf[ni][0] = f2b(Vs[(ks * 8 + tg) * ASTR + ni * 8 + g]);
                bf[ni][1] = f2b(Vs[(ks * 8 + tg + 4) * ASTR + ni * 8 + g]);
            }
            #pragma unroll
            for (int ni = 0; ni < 8; ni++)
                MMA_TF32(O[ni], af, bf[ni]);
        }
    }

    // ---- normalize + store y[b, t, h*64 + d] ----
    const float inv0 = 1.0f / li0;
    const float inv1 = 1.0f / li1;
    float* y0 = g_y + (size_t)(b * TT + row0) * DD + h * HD;
    float* y1 = g_y + (size_t)(b * TT + row1) * DD + h * HD;
    #pragma unroll
    for (int ni = 0; ni < 8; ni++) {
        const int c = ni * 8 + 2 * tg;
        float2 v0; v0.x = O[ni][0] * inv0; v0.y = O[ni][1] * inv0;
        *(float2*)&y0[c] = v0;
        float2 v1; v1.x = O[ni][2] * inv1; v1.y = O[ni][3] * inv1;
        *(float2*)&y1[c] = v1;
    }
}

// ---------------------------------------------------------------------------
extern "C" void kernel_launch(void* const* d_in, const int* in_sizes, int n_in,
                              void* d_out, int out_size)
{
    (void)in_sizes; (void)n_in; (void)out_size;
    const float* x      = (const float*)d_in[0];
    const float* W_attn = (const float*)d_in[1];
    const float* b_attn = (const float*)d_in[2];
    const float* W_proj = (const float*)d_in[3];
    const float* b_proj = (const float*)d_in[4];
    float* out = (float*)d_out;

    float* gy = nullptr;
    cudaGetSymbolAddress((void**)&gy, g_y);

    static bool attr_done = false;
    if (!attr_done) {
        cudaFuncSetAttribute(mma_gemm<0, N3>, cudaFuncAttributeMaxDynamicSharedMemorySize, SMEM_GEMM);
        cudaFuncSetAttribute(mma_gemm<1, DD>, cudaFuncAttributeMaxDynamicSharedMemorySize, SMEM_GEMM);
        cudaFuncSetAttribute(attn_tc, cudaFuncAttributeMaxDynamicSharedMemorySize, SMEM_ATTN);
        attr_done = true;
    }

    // 1) QKV projection (mma.sync tf32) + head-layout scatter
    mma_gemm<0, N3><<<dim3(N3 / 128, MM / 128), 256, SMEM_GEMM>>>(x, W_attn, b_attn, nullptr);

    // 2) causal flash attention (mma.sync tf32)
    attn_tc<<<dim3(TT / 128, HH, BB), 256, SMEM_ATTN>>>();

    // 3) output projection (mma.sync tf32)
    mma_gemm<1, DD><<<dim3(DD / 128, MM / 128), 256, SMEM_GEMM>>>(gy, W_proj, b_proj, out);
}